// round 10
// baseline (speedup 1.0000x reference)
#include <cuda_runtime.h>
#include <math.h>

#define N_NODES 50000
#define N_EDGES 800000
#define F_IN    32
#define H_DIM   64
#define C_OUT   7
#define C_PAD   8
#define BN_EPS  1e-5f

typedef unsigned long long ull;

// ---------------- scratch (device globals; no allocation) ----------------
__device__ __align__(128) float  g_Y0[N_NODES * H_DIM];     // x @ W[0]
__device__ __align__(128) float  g_Y1[N_NODES * H_DIM];     // x @ (W[1]-W[0])
__device__ __align__(128) float  g_Z [N_NODES * H_DIM];     // x @ R + B
__device__ __align__(128) float  g_A [N_NODES * H_DIM];     // aggregation accumulator
__device__ __align__(128) float  g_H [N_NODES * H_DIM];     // hidden activations
__device__ __align__(128) float2 g_edge[N_EDGES];           // src-CSR payload: (dst bits, u)
__device__ __align__(128) int    g_cnt_out[N_NODES];        // out-degree (CSR key)
__device__ __align__(128) int    g_cnt_in [N_NODES];        // in-degree (for mean)
__device__ __align__(128) int    g_off[N_NODES + 1];        // src-CSR offsets
__device__ __align__(128) int    g_cur[N_NODES];            // placement cursors
__device__ __align__(16)  float  g_WT0[3 * 64 * 64];        // transposed weights per layer
__device__ __align__(16)  float  g_WT1[3 * 64 * 64];
__device__ __align__(16)  float  g_WT2[3 * 64 * 64];

// ---------------- packed fp32x2 helpers ----------------
__device__ __forceinline__ ull fma2(ull a, ull b, ull c) {
    ull d;
    asm("fma.rn.f32x2 %0, %1, %2, %3;" : "=l"(d) : "l"(a), "l"(b), "l"(c));
    return d;
}
__device__ __forceinline__ float fold2(ull v) {
    float lo, hi;
    asm("mov.b64 {%0,%1}, %2;" : "=f"(lo), "=f"(hi) : "l"(v));
    return lo + hi;
}

// ---------------- CSR build ----------------
__global__ void zero_cnt_kernel() {
    int i = blockIdx.x * blockDim.x + threadIdx.x;
    if (i < N_NODES) { g_cnt_out[i] = 0; g_cnt_in[i] = 0; }
}

__global__ void deg_kernel(const int* __restrict__ ei) {
    int e = blockIdx.x * blockDim.x + threadIdx.x;
    if (e < N_EDGES) {
        atomicAdd(&g_cnt_out[ei[e]], 1);
        atomicAdd(&g_cnt_in [ei[N_EDGES + e]], 1);
    }
}

// single-block exclusive scan of g_cnt_out -> g_off, g_cur
__global__ void __launch_bounds__(1024) scan_kernel() {
    __shared__ int ssum[1024];
    const int NPT = (N_NODES + 1023) / 1024;
    int t = threadIdx.x;
    int base = t * NPT;

    int local = 0;
    for (int i = 0; i < NPT; i++) {
        int idx = base + i;
        if (idx < N_NODES) local += g_cnt_out[idx];
    }
    ssum[t] = local;
    __syncthreads();

    for (int d = 1; d < 1024; d <<= 1) {
        int v = (t >= d) ? ssum[t - d] : 0;
        __syncthreads();
        ssum[t] += v;
        __syncthreads();
    }

    int run = (t > 0) ? ssum[t - 1] : 0;
    for (int i = 0; i < NPT; i++) {
        int idx = base + i;
        if (idx < N_NODES) {
            g_off[idx] = run;
            g_cur[idx] = run;
            run += g_cnt_out[idx];
        }
    }
    if (t == 0) g_off[N_NODES] = ssum[1023];
}

__global__ void build_kernel(const int* __restrict__ ei, const float* __restrict__ ea) {
    int e = blockIdx.x * blockDim.x + threadIdx.x;
    if (e >= N_EDGES) return;
    int s = ei[e];
    int d = ei[N_EDGES + e];
    int p = atomicAdd(&g_cur[s], 1);
    g_edge[p] = make_float2(__int_as_float(d), ea[e]);
}

// ---------------- weight transpose: WT[0][o][c]=W0, WT[1][o][c]=W1-W0, WT[2][o][c]=R ----------------
__global__ void prepw_kernel(const float* __restrict__ W, const float* __restrict__ R,
                             int cin, int cout, int sel)
{
    float* WT = (sel == 0) ? g_WT0 : (sel == 1) ? g_WT1 : g_WT2;
    int t = blockIdx.x * blockDim.x + threadIdx.x;
    if (t >= cin * cout) return;
    int o = t / cin, c = t % cin;
    float w0 = W[c * cout + o];
    float w1 = W[cin * cout + c * cout + o];
    WT[o * cin + c]                  = w0;
    WT[cout * cin + o * cin + c]     = w1 - w0;
    WT[2 * cout * cin + o * cin + c] = R[c * cout + o];
}

// ---------------- fused node GEMM (f32x2 packed): Y0, Y1, Z; also zeroes g_A ----------------
template<int CIN, int COUT, int COUTP, int NT>
__global__ void __launch_bounds__(256)
gemm3_kernel(const float* __restrict__ Xext,
             const float* __restrict__ B,
             int sel, int use_h)
{
    constexpr int TY    = 256 / COUTP;
    constexpr int NODES = TY * NT;
    __shared__ float sx[NODES][CIN];

    const float* WT = (sel == 0) ? g_WT0 : (sel == 1) ? g_WT1 : g_WT2;
    const float* X  = use_h ? (const float*)g_H : Xext;

    int nbase = blockIdx.x * NODES;
    int tid = threadIdx.y * COUTP + threadIdx.x;

    constexpr int NV = NODES * CIN / 4;
    const float4* X4 = reinterpret_cast<const float4*>(X);
    float4* sx4 = reinterpret_cast<float4*>(&sx[0][0]);
    #pragma unroll
    for (int i = tid; i < NV; i += 256) {
        int nn = nbase + i / (CIN / 4);
        float4 v = make_float4(0.f, 0.f, 0.f, 0.f);
        if (nn < N_NODES) v = X4[nn * (CIN / 4) + (i % (CIN / 4))];
        sx4[i] = v;
    }
    __syncthreads();

    int o  = threadIdx.x;
    int nb = threadIdx.y * NT;

    ull a0[NT], a1[NT], az[NT];
    #pragma unroll
    for (int j = 0; j < NT; j++) { a0[j] = 0ULL; a1[j] = 0ULL; az[j] = 0ULL; }

    if (o < COUT) {
        const ulonglong2* w0p = reinterpret_cast<const ulonglong2*>(WT + o * CIN);
        const ulonglong2* w1p = reinterpret_cast<const ulonglong2*>(WT + COUT * CIN + o * CIN);
        const ulonglong2* wrp = reinterpret_cast<const ulonglong2*>(WT + 2 * COUT * CIN + o * CIN);
        #pragma unroll 4
        for (int cq = 0; cq < CIN / 4; cq++) {
            ulonglong2 w0 = w0p[cq];
            ulonglong2 dw = w1p[cq];
            ulonglong2 wr = wrp[cq];
            #pragma unroll
            for (int j = 0; j < NT; j++) {
                ulonglong2 xv = *reinterpret_cast<const ulonglong2*>(&sx[nb + j][cq * 4]);
                a0[j] = fma2(xv.x, w0.x, a0[j]);
                a0[j] = fma2(xv.y, w0.y, a0[j]);
                a1[j] = fma2(xv.x, dw.x, a1[j]);
                a1[j] = fma2(xv.y, dw.y, a1[j]);
                az[j] = fma2(xv.x, wr.x, az[j]);
                az[j] = fma2(xv.y, wr.y, az[j]);
            }
        }
    }

    float b = (o < COUT) ? B[o] : 0.f;
    #pragma unroll
    for (int j = 0; j < NT; j++) {
        int n = nbase + nb + j;
        if (n < N_NODES) {
            g_Y0[n * COUTP + o] = fold2(a0[j]);
            g_Y1[n * COUTP + o] = fold2(a1[j]);
            g_Z [n * COUTP + o] = fold2(az[j]) + b;   // pad cols exact 0
            g_A [n * COUTP + o] = 0.f;
        }
    }
}

// ---------------- src-CSR scatter: warp owns src, Y row in registers, red.v4 to dst ----------------
template<int COUTP>
__global__ void __launch_bounds__(256)
scatter_csr_kernel()
{
    constexpr int LPR = COUTP / 4;     // lanes per row (16 for 64ch, 2 for 8ch)
    constexpr int GRP = 32 / LPR;      // edges processed per warp-iteration
    int w = (blockIdx.x * blockDim.x + threadIdx.x) >> 5;
    if (w >= N_NODES) return;
    int lane = threadIdx.x & 31;
    int grp  = lane / LPR;
    int q    = lane % LPR;

    int beg = g_off[w];
    int end = g_off[w + 1];
    if (beg == end) return;

    const float4* Y0 = reinterpret_cast<const float4*>(g_Y0);
    const float4* Y1 = reinterpret_cast<const float4*>(g_Y1);
    float4 y0 = Y0[w * LPR + q];
    float4 y1 = Y1[w * LPR + q];

    #pragma unroll 2
    for (int e = beg + grp; e < end; e += GRP) {
        float2 rec = g_edge[e];
        int   d = __float_as_int(rec.x);
        float u = rec.y;
        float4 m;
        m.x = fmaf(u, y1.x, y0.x);
        m.y = fmaf(u, y1.y, y0.y);
        m.z = fmaf(u, y1.z, y0.z);
        m.w = fmaf(u, y1.w, y0.w);
        float* dst = &g_A[d * COUTP + q * 4];
        asm volatile("red.global.add.v4.f32 [%0], {%1,%2,%3,%4};"
                     :: "l"(dst), "f"(m.x), "f"(m.y), "f"(m.z), "f"(m.w) : "memory");
    }
}

// ---------------- epilogue: mean + residual + BN + ELU -> g_H (float4) ----------------
__global__ void __launch_bounds__(256)
epi_bn_kernel(const float* __restrict__ G,  const float* __restrict__ BE,
              const float* __restrict__ RM, const float* __restrict__ RV)
{
    int i4 = blockIdx.x * blockDim.x + threadIdx.x;
    if (i4 >= N_NODES * (H_DIM / 4)) return;
    int n  = i4 >> 4;
    int oq = i4 & 15;

    int cnt = g_cnt_in[n];
    float inv = 1.f / (float)(cnt < 1 ? 1 : cnt);

    float4 a = reinterpret_cast<const float4*>(g_A)[i4];
    float4 z = reinterpret_cast<const float4*>(g_Z)[i4];
    float4 g4  = reinterpret_cast<const float4*>(G )[oq];
    float4 be4 = reinterpret_cast<const float4*>(BE)[oq];
    float4 rm4 = reinterpret_cast<const float4*>(RM)[oq];
    float4 rv4 = reinterpret_cast<const float4*>(RV)[oq];

    float4 v;
    v.x = (a.x * inv + z.x - rm4.x) * rsqrtf(rv4.x + BN_EPS) * g4.x + be4.x;
    v.y = (a.y * inv + z.y - rm4.y) * rsqrtf(rv4.y + BN_EPS) * g4.y + be4.y;
    v.z = (a.z * inv + z.z - rm4.z) * rsqrtf(rv4.z + BN_EPS) * g4.z + be4.z;
    v.w = (a.w * inv + z.w - rm4.w) * rsqrtf(rv4.w + BN_EPS) * g4.w + be4.w;
    v.x = (v.x > 0.f) ? v.x : expm1f(v.x);
    v.y = (v.y > 0.f) ? v.y : expm1f(v.y);
    v.z = (v.z > 0.f) ? v.z : expm1f(v.z);
    v.w = (v.w > 0.f) ? v.w : expm1f(v.w);

    reinterpret_cast<float4*>(g_H)[i4] = v;
}

// ---------------- final: mean + residual + log_softmax (8 lanes per node) ----------------
__global__ void __launch_bounds__(256)
final_kernel(float* __restrict__ out)
{
    int t    = blockIdx.x * blockDim.x + threadIdx.x;
    int node = t >> 3;
    int o    = t & 7;
    if (node >= N_NODES) return;

    int cnt = g_cnt_in[node];
    float inv = 1.f / (float)(cnt < 1 ? 1 : cnt);
    float v = g_A[node * C_PAD + o] * inv + g_Z[node * C_PAD + o];

    float vm = (o < C_OUT) ? v : -INFINITY;
    float mx = vm;
    #pragma unroll
    for (int d = 1; d < 8; d <<= 1)
        mx = fmaxf(mx, __shfl_xor_sync(0xFFFFFFFFu, mx, d));

    float ex = (o < C_OUT) ? __expf(v - mx) : 0.f;
    float s  = ex;
    #pragma unroll
    for (int d = 1; d < 8; d <<= 1)
        s += __shfl_xor_sync(0xFFFFFFFFu, s, d);

    float lse = mx + logf(s);
    if (o < C_OUT) out[node * C_OUT + o] = v - lse;
}

// ---------------- launch ----------------
extern "C" void kernel_launch(void* const* d_in, const int* in_sizes, int n_in,
                              void* d_out, int out_size)
{
    const float* x   = (const float*)d_in[0];
    const int*   ei  = (const int*)  d_in[1];
    const float* ea  = (const float*)d_in[2];
    const float* W0  = (const float*)d_in[3];
    const float* R0  = (const float*)d_in[4];
    const float* B0  = (const float*)d_in[5];
    const float* W1  = (const float*)d_in[6];
    const float* R1  = (const float*)d_in[7];
    const float* B1  = (const float*)d_in[8];
    const float* W2  = (const float*)d_in[9];
    const float* R2  = (const float*)d_in[10];
    const float* B2  = (const float*)d_in[11];
    const float* G0  = (const float*)d_in[12];
    const float* BE0 = (const float*)d_in[13];
    const float* RM0 = (const float*)d_in[14];
    const float* RV0 = (const float*)d_in[15];
    const float* G1  = (const float*)d_in[16];
    const float* BE1 = (const float*)d_in[17];
    const float* RM1 = (const float*)d_in[18];
    const float* RV1 = (const float*)d_in[19];
    float* out = (float*)d_out;

    // ---- src-CSR build (once; reused by all 3 layers) ----
    zero_cnt_kernel<<<(N_NODES + 255) / 256, 256>>>();
    deg_kernel<<<(N_EDGES + 255) / 256, 256>>>(ei);
    scan_kernel<<<1, 1024>>>();
    build_kernel<<<(N_EDGES + 255) / 256, 256>>>(ei, ea);

    // ---- weight transposes ----
    prepw_kernel<<<(F_IN * H_DIM + 255) / 256, 256>>>(W0, R0, F_IN,  H_DIM, 0);
    prepw_kernel<<<(H_DIM * H_DIM + 255) / 256, 256>>>(W1, R1, H_DIM, H_DIM, 1);
    prepw_kernel<<<(H_DIM * C_OUT + 255) / 256, 256>>>(W2, R2, H_DIM, C_OUT, 2);

    // ---- Layer 0: 32 -> 64 ----
    gemm3_kernel<32, 64, 64, 8><<<(N_NODES + 31) / 32, dim3(64, 4)>>>(x, B0, 0, 0);
    scatter_csr_kernel<64><<<(N_NODES * 32 + 255) / 256, 256>>>();
    epi_bn_kernel<<<(N_NODES * 16 + 255) / 256, 256>>>(G0, BE0, RM0, RV0);

    // ---- Layer 1: 64 -> 64 ----
    gemm3_kernel<64, 64, 64, 8><<<(N_NODES + 31) / 32, dim3(64, 4)>>>(nullptr, B1, 1, 1);
    scatter_csr_kernel<64><<<(N_NODES * 32 + 255) / 256, 256>>>();
    epi_bn_kernel<<<(N_NODES * 16 + 255) / 256, 256>>>(G1, BE1, RM1, RV1);

    // ---- Layer 2: 64 -> 7 (pad 8) ----
    gemm3_kernel<64, 7, 8, 2><<<(N_NODES + 63) / 64, dim3(8, 32)>>>(nullptr, B2, 2, 1);
    scatter_csr_kernel<8><<<(N_NODES * 32 + 255) / 256, 256>>>();
    final_kernel<<<(N_NODES * 8 + 255) / 256, 256>>>(out);
}